// round 9
// baseline (speedup 1.0000x reference)
#include <cuda_runtime.h>
#include <math.h>
#include <stdint.h>

// Problem constants
#define B_TOT   4096
#define T_STEPS 25
#define K_ENS   8
#define OBS     64
#define ACT     16
#define IN1     80            // OBS + ACT
#define HID     512
#define OUTD    129           // 2*OBS + 1
#define TM      32            // rows per CTA tile
#define RT_THREADS 512
#define SETUP_THREADS 256
#define MAXTILES 136
#define OUT_STRIDE 132        // padded 129
#define CHK     16            // k-rows per weight chunk

// Dynamic smem layout (floats):
//  sh_x   : TM*IN1        = 2560
//  sh_h1  : TM*HID        = 16384
//  sh_h2  : TM*HID        = 16384
//  sh_out : TM*OUT_STRIDE = 4224
//  sh_w   : 2*CHK*HID     = 16384   (weight double-buffer, 2 x 32KB)
#define SMEM_FLOATS (TM*IN1 + 2*TM*HID + TM*OUT_STRIDE + 2*CHK*HID)
#define SMEM_BYTES  (SMEM_FLOATS * 4)

#define WCHUNK_BYTES   (CHK*HID*4)        // 32768 for layers 1,2
#define W3CHUNK_BYTES  (CHK*OUTD*4)       // 8256 for layer 3

// ---- scratch in device globals (no allocation allowed) ----
__device__ int g_perm[B_TOT];
__device__ int g_tileK[MAXTILES];
__device__ int g_tileStart[MAXTILES];
__device__ int g_tileRows[MAXTILES];
__device__ int g_ntiles;

// ---- packed f32x2 helpers ----
typedef unsigned long long u64;
__device__ __forceinline__ u64 pack_dup(float a) {
    u64 d;
    unsigned int ai = __float_as_uint(a);
    asm("mov.b64 %0, {%1, %1};" : "=l"(d) : "r"(ai));
    return d;
}
__device__ __forceinline__ void fma2(u64& d, u64 a, u64 b, u64 c) {
    asm("fma.rn.f32x2 %0, %1, %2, %3;" : "=l"(d) : "l"(a), "l"(b), "l"(c));
}
__device__ __forceinline__ void unpack2(float& lo, float& hi, u64 v) {
    unsigned int l, h;
    asm("mov.b64 {%0, %1}, %2;" : "=r"(l), "=r"(h) : "l"(v));
    lo = __uint_as_float(l);
    hi = __uint_as_float(h);
}

// ---- mbarrier / bulk-async PTX macros ----
#define MBAR_INIT(addr, cnt) \
    asm volatile("mbarrier.init.shared.b64 [%0], %1;" :: "r"(addr), "r"(cnt) : "memory")
#define MBAR_EXPECT_TX(addr, bytes) \
    asm volatile("mbarrier.arrive.expect_tx.shared.b64 _, [%0], %1;" :: "r"(addr), "r"(bytes) : "memory")
#define MBAR_ARRIVE(addr) \
    asm volatile("mbarrier.arrive.shared.b64 _, [%0];" :: "r"(addr) : "memory")
#define MBAR_WAIT_ACQ(addr, ph) do { unsigned _done = 0; \
    while (!_done) { \
        asm volatile("{\n\t.reg .pred p;\n\t" \
            "mbarrier.try_wait.parity.acquire.cta.shared::cta.b64 p, [%1], %2, 0x989680;\n\t" \
            "selp.b32 %0, 1, 0, p;\n\t}" \
            : "=r"(_done) : "r"(addr), "r"((unsigned)(ph)) : "memory"); \
    } } while (0)
#define MBAR_WAIT_RLX(addr, ph) do { unsigned _done = 0; \
    while (!_done) { \
        asm volatile("{\n\t.reg .pred p;\n\t" \
            "mbarrier.try_wait.parity.relaxed.cta.shared::cta.b64 p, [%1], %2, 0x989680;\n\t" \
            "selp.b32 %0, 1, 0, p;\n\t}" \
            : "=r"(_done) : "r"(addr), "r"((unsigned)(ph)) : "memory"); \
    } } while (0)
#define CP_BULK(dst_smem, src_gmem, bytes, mbar) \
    asm volatile("cp.async.bulk.shared::cluster.global.mbarrier::complete_tx::bytes [%0], [%1], %2, [%3];" \
        :: "r"(dst_smem), "l"(src_gmem), "r"(bytes), "r"(mbar) : "memory")

__device__ __forceinline__ uint32_t smem_u32(const void* p) {
    uint32_t a;
    asm("{ .reg .u64 t; cvta.to.shared.u64 t, %1; cvt.u32.u64 %0, t; }" : "=r"(a) : "l"(p));
    return a;
}

// ============================================================
// Setup: dtype-detect (int32 vs int64) + counting sort by
// ensemble assignment + 32-row tile metadata. One block.
// ============================================================
__global__ void setup_kernel(const int* __restrict__ assign_raw) {
    __shared__ int cnt[K_ENS];
    __shared__ int cur[K_ENS];
    __shared__ int odd_nonzero;
    int tid = threadIdx.x;
    if (tid < K_ENS) cnt[tid] = 0;
    if (tid == 0) odd_nonzero = 0;
    __syncthreads();

    int local_nz = 0;
    for (int w = 2 * tid + 1; w < B_TOT; w += 2 * SETUP_THREADS)
        if (assign_raw[w] != 0) local_nz = 1;
    if (local_nz) atomicOr(&odd_nonzero, 1);
    __syncthreads();
    const bool is_i32 = (odd_nonzero != 0);

    for (int b = tid; b < B_TOT; b += SETUP_THREADS) {
        int k = is_i32 ? assign_raw[b] : assign_raw[2 * b];
        atomicAdd(&cnt[k], 1);
    }
    __syncthreads();
    if (tid == 0) {
        int off = 0, nt = 0;
        for (int k = 0; k < K_ENS; k++) {
            cur[k] = off;
            int c = cnt[k];
            for (int s = 0; s < c; s += TM) {
                g_tileK[nt] = k;
                g_tileStart[nt] = off + s;
                g_tileRows[nt] = (c - s < TM) ? (c - s) : TM;
                nt++;
            }
            off += c;
        }
        g_ntiles = nt;
        for (int e = nt; e < MAXTILES; e++) g_tileRows[e] = 0;
    }
    __syncthreads();
    for (int b = tid; b < B_TOT; b += SETUP_THREADS) {
        int k = is_i32 ? assign_raw[b] : assign_raw[2 * b];
        int pos = atomicAdd(&cur[k], 1);
        g_perm[pos] = b;
    }
}

// ============================================================
// Math helpers
// ============================================================
__device__ __forceinline__ float softplusf(float z) {
    return (z > 0.f) ? (z + log1pf(__expf(-z))) : log1pf(__expf(z));
}
__device__ __forceinline__ float swishf(float x) {
    return x * __frcp_rn(1.f + __expf(-x));
}

// Accumulate one 16-k weight chunk (smem) into packed acc.
// wc: [CHK][512] smem. Thread covers cols tx*4..tx*4+3 (2 packed pairs)
// and 8 rows (ty*8+jr). Activations loaded float4 along k (broadcast).
template<int INSTRIDE>
__device__ __forceinline__ void chunk_dense(
    const float* __restrict__ wc,
    const float* __restrict__ abase,   // sh_in + (ty*8)*INSTRIDE + k0
    u64 acc[8][2], int tx)
{
    const float* wb = wc + tx * 4;
#pragma unroll
    for (int i0 = 0; i0 < CHK; i0 += 4) {
        float4 a4[8];
#pragma unroll
        for (int jr = 0; jr < 8; jr++)
            a4[jr] = *(const float4*)(abase + jr * INSTRIDE + i0);
#pragma unroll
        for (int u = 0; u < 4; u++) {
            ulonglong2 w = *(const ulonglong2*)(wb + (i0 + u) * HID);
            u64 wp0 = w.x, wp1 = w.y;
#pragma unroll
            for (int jr = 0; jr < 8; jr++) {
                float av = (u == 0) ? a4[jr].x : (u == 1) ? a4[jr].y
                         : (u == 2) ? a4[jr].z : a4[jr].w;
                u64 a2 = pack_dup(av);
                fma2(acc[jr][0], a2, wp0, acc[jr][0]);
                fma2(acc[jr][1], a2, wp1, acc[jr][1]);
            }
        }
    }
}

// Accumulate one 16-k chunk of the 129-col output layer.
// wc: [CHK][129] smem. tx3 in 0..31 (cols tx3+32*jc, +128 for tx3==0),
// ty3 in 0..15 (2 rows each).
__device__ __forceinline__ void chunk_out(
    const float* __restrict__ wc,
    const float* __restrict__ abase,   // sh_in + (ty3*2)*HID + k0
    float acc[2][5], int tx3, bool has128)
{
#pragma unroll 4
    for (int i = 0; i < CHK; i++) {
        const float* wr = wc + i * OUTD + tx3;
        float wv[5];
#pragma unroll
        for (int jc = 0; jc < 4; jc++) wv[jc] = wr[jc * 32];
        wv[4] = has128 ? wr[128] : 0.f;
        float a[2];
#pragma unroll
        for (int jr = 0; jr < 2; jr++) a[jr] = abase[jr * HID + i];
#pragma unroll
        for (int jr = 0; jr < 2; jr++)
#pragma unroll
            for (int jc = 0; jc < 5; jc++)
                acc[jr][jc] = fmaf(a[jr], wv[jc], acc[jr][jc]);
    }
}

// ============================================================
// Persistent rollout: one CTA (512 threads) = 32 same-member
// batch rows, all 25 timesteps local; weights double-buffered
// in smem via cp.async.bulk + mbarrier.
// ============================================================
__global__ void __launch_bounds__(RT_THREADS, 1) rollout_kernel(
    const float* __restrict__ obs,
    const float* __restrict__ acts,
    const float* __restrict__ W1, const float* __restrict__ b1,
    const float* __restrict__ W2, const float* __restrict__ b2,
    const float* __restrict__ W3, const float* __restrict__ b3,
    const float* __restrict__ maxlv, const float* __restrict__ minlv,
    const float* __restrict__ noise,
    float* __restrict__ out_obs,
    float* __restrict__ out_rew)
{
    const int tile = blockIdx.x;
    if (tile >= g_ntiles) return;
    const int nrows = g_tileRows[tile];
    const int k     = g_tileK[tile];
    const int start = g_tileStart[tile];

    extern __shared__ float sh[];
    float* sh_x   = sh;                              // [TM][IN1]
    float* sh_h1  = sh_x + TM * IN1;                 // [TM][HID]
    float* sh_h2  = sh_h1 + TM * HID;                // [TM][HID]
    float* sh_out = sh_h2 + TM * HID;                // [TM][OUT_STRIDE]
    float* sh_w   = sh_out + TM * OUT_STRIDE;        // [2][CHK*HID]
    __shared__ int rows[TM];
    __shared__ unsigned long long mb[4];             // full0, full1, empty0, empty1

    const int tid = threadIdx.x;
    const int tx = tid & 127, ty = tid >> 7;         // 128 col-groups x 4 row-groups
    const int tx3 = tid & 31, ty3 = tid >> 5;        // 32 col-groups x 16 row-groups
    const bool has128 = (tx3 == 0);

    const uint32_t mb_base = smem_u32(mb);
    const uint32_t full_a[2]  = {mb_base,      mb_base + 8};
    const uint32_t empty_a[2] = {mb_base + 16, mb_base + 24};
    const uint32_t wbuf_a[2]  = {smem_u32(sh_w), smem_u32(sh_w) + WCHUNK_BYTES};
    const float*   wbuf_p[2]  = {sh_w, sh_w + CHK * HID};

    if (tid < TM) rows[tid] = (tid < nrows) ? g_perm[start + tid] : 0;
    if (tid == 0) {
        MBAR_INIT(full_a[0], 1);
        MBAR_INIT(full_a[1], 1);
        MBAR_INIT(empty_a[0], RT_THREADS);
        MBAR_INIT(empty_a[1], RT_THREADS);
    }

    const float* W1k = W1 + (size_t)k * IN1 * HID;
    const float* W2k = W2 + (size_t)k * HID * HID;
    const float* W3k = W3 + (size_t)k * HID * OUTD;
    const float* b1k = b1 + (size_t)k * HID;
    const float* b2k = b2 + (size_t)k * HID;
    const float* b3k = b3 + (size_t)k * OUTD;

    float bias1[4], bias2[4];
#pragma unroll
    for (int jc = 0; jc < 4; jc++) {
        bias1[jc] = __ldg(b1k + tx * 4 + jc);
        bias2[jc] = __ldg(b2k + tx * 4 + jc);
    }
    float bias3[5];
#pragma unroll
    for (int jc = 0; jc < 4; jc++) bias3[jc] = __ldg(b3k + tx3 + jc * 32);
    bias3[4] = has128 ? __ldg(b3k + 128) : 0.f;

    __syncthreads();   // rows[] + mbarrier init visible

    // ---- pipeline cursors (deterministic, tracked by all threads) ----
    unsigned use_i[2] = {0, 0}; int slot_i = 0;
    unsigned use_c[2] = {0, 0}; int slot_c = 0;

#define ISSUE_CHUNK(srcptr, bytes) do { \
        int _s = slot_i; unsigned _u = use_i[_s]; \
        if (tid == 0) { \
            if (_u >= 1) MBAR_WAIT_RLX(empty_a[_s], (_u - 1) & 1); \
            MBAR_EXPECT_TX(full_a[_s], (unsigned)(bytes)); \
            CP_BULK(wbuf_a[_s], (const char*)(srcptr), (unsigned)(bytes), full_a[_s]); \
        } \
        use_i[_s] = _u + 1; slot_i ^= 1; \
    } while (0)

#define WAIT_FULL(sv) do { sv = slot_c; MBAR_WAIT_ACQ(full_a[sv], use_c[sv] & 1); } while (0)
#define DONE_CHUNK() do { MBAR_ARRIVE(empty_a[slot_c]); use_c[slot_c]++; slot_c ^= 1; } while (0)

    // Init state
    for (int idx = tid; idx < TM * OBS; idx += RT_THREADS) {
        int r = idx >> 6, d = idx & 63;
        sh_x[r * IN1 + d] = (r < nrows) ? obs[(size_t)rows[r] * OBS + d] : 0.f;
    }
    for (int idx = tid; idx < TM * ACT; idx += RT_THREADS) {
        int r = idx >> 4, a = idx & 15;
        sh_x[r * IN1 + OBS + a] = 0.f;
    }

    for (int t = 0; t < T_STEPS; t++) {
        for (int idx = tid; idx < TM * ACT; idx += RT_THREADS) {
            int r = idx >> 4, a = idx & 15;
            if (r < nrows)
                sh_x[r * IN1 + OBS + a] =
                    acts[((size_t)rows[r] * T_STEPS + t) * ACT + a];
        }
        __syncthreads();

        // ================= layer 1: x[80] -> h1[512] =================
        {
            const int NCH = IN1 / CHK;   // 5
            u64 acc[8][2];
#pragma unroll
            for (int jr = 0; jr < 8; jr++) { acc[jr][0] = 0ull; acc[jr][1] = 0ull; }

            ISSUE_CHUNK((const char*)W1k, WCHUNK_BYTES);
            for (int c = 0; c < NCH; c++) {
                if (c + 1 < NCH)
                    ISSUE_CHUNK((const char*)W1k + (size_t)(c + 1) * WCHUNK_BYTES, WCHUNK_BYTES);
                int s; WAIT_FULL(s);
                chunk_dense<IN1>(wbuf_p[s], sh_x + (ty * 8) * IN1 + c * CHK, acc, tx);
                DONE_CHUNK();
            }
#pragma unroll
            for (int jr = 0; jr < 8; jr++) {
                float v0, v1, v2, v3;
                unpack2(v0, v1, acc[jr][0]);
                unpack2(v2, v3, acc[jr][1]);
                v0 = swishf(v0 + bias1[0]); v1 = swishf(v1 + bias1[1]);
                v2 = swishf(v2 + bias1[2]); v3 = swishf(v3 + bias1[3]);
                *(float4*)(sh_h1 + (ty * 8 + jr) * HID + tx * 4) = make_float4(v0, v1, v2, v3);
            }
        }
        __syncthreads();

        // ================= layer 2: h1[512] -> h2[512] =================
        {
            const int NCH = HID / CHK;   // 32
            u64 acc[8][2];
#pragma unroll
            for (int jr = 0; jr < 8; jr++) { acc[jr][0] = 0ull; acc[jr][1] = 0ull; }

            ISSUE_CHUNK((const char*)W2k, WCHUNK_BYTES);
            for (int c = 0; c < NCH; c++) {
                if (c + 1 < NCH)
                    ISSUE_CHUNK((const char*)W2k + (size_t)(c + 1) * WCHUNK_BYTES, WCHUNK_BYTES);
                int s; WAIT_FULL(s);
                chunk_dense<HID>(wbuf_p[s], sh_h1 + (ty * 8) * HID + c * CHK, acc, tx);
                DONE_CHUNK();
            }
#pragma unroll
            for (int jr = 0; jr < 8; jr++) {
                float v0, v1, v2, v3;
                unpack2(v0, v1, acc[jr][0]);
                unpack2(v2, v3, acc[jr][1]);
                v0 = swishf(v0 + bias2[0]); v1 = swishf(v1 + bias2[1]);
                v2 = swishf(v2 + bias2[2]); v3 = swishf(v3 + bias2[3]);
                *(float4*)(sh_h2 + (ty * 8 + jr) * HID + tx * 4) = make_float4(v0, v1, v2, v3);
            }
        }
        __syncthreads();

        // ================= layer 3: h2[512] -> out[129] =================
        {
            const int NCH = HID / CHK;   // 32
            float acc[2][5];
#pragma unroll
            for (int jr = 0; jr < 2; jr++)
#pragma unroll
                for (int jc = 0; jc < 5; jc++) acc[jr][jc] = 0.f;

            ISSUE_CHUNK((const char*)W3k, W3CHUNK_BYTES);
            for (int c = 0; c < NCH; c++) {
                if (c + 1 < NCH)
                    ISSUE_CHUNK((const char*)W3k + (size_t)(c + 1) * W3CHUNK_BYTES, W3CHUNK_BYTES);
                int s; WAIT_FULL(s);
                chunk_out(wbuf_p[s], sh_h2 + (ty3 * 2) * HID + c * CHK, acc, tx3, has128);
                DONE_CHUNK();
            }
#pragma unroll
            for (int jr = 0; jr < 2; jr++) {
#pragma unroll
                for (int jc = 0; jc < 5; jc++) {
                    int col = tx3 + jc * 32;
                    if (col < OUTD)
                        sh_out[(ty3 * 2 + jr) * OUT_STRIDE + col] = acc[jr][jc] + bias3[jc];
                }
            }
        }
        __syncthreads();

        // ================= postprocess =================
        const float* nz_t = noise + ((size_t)t * K_ENS + k) * B_TOT * OBS;
        for (int idx = tid; idx < TM * OBS; idx += RT_THREADS) {
            int r = idx >> 6, d = idx & 63;
            if (r < nrows) {
                int row = rows[r];
                float mean = sh_out[r * OUT_STRIDE + d];
                float lv   = sh_out[r * OUT_STRIDE + OBS + d];
                float mx = __ldg(maxlv + d), mn = __ldg(minlv + d);
                lv = mx - softplusf(mx - lv);
                lv = mn + softplusf(lv - mn);
                float nz = __ldg(nz_t + (size_t)row * OBS + d);
                float no = fmaf(nz, __expf(0.5f * lv), mean);
                out_obs[((size_t)row * T_STEPS + t) * OBS + d] = no;
                sh_x[r * IN1 + d] = no;
            }
        }
        if (tid < nrows)
            out_rew[(size_t)rows[tid] * T_STEPS + t] = sh_out[tid * OUT_STRIDE + 128];
        __syncthreads();
    }
#undef ISSUE_CHUNK
#undef WAIT_FULL
#undef DONE_CHUNK
}

// ============================================================
// Launch
// ============================================================
extern "C" void kernel_launch(void* const* d_in, const int* in_sizes, int n_in,
                              void* d_out, int out_size) {
    const float* obs   = (const float*)d_in[0];
    const float* acts  = (const float*)d_in[1];
    const float* W1    = (const float*)d_in[2];
    const float* b1    = (const float*)d_in[3];
    const float* W2    = (const float*)d_in[4];
    const float* b2    = (const float*)d_in[5];
    const float* W3    = (const float*)d_in[6];
    const float* b3    = (const float*)d_in[7];
    const float* maxlv = (const float*)d_in[8];
    const float* minlv = (const float*)d_in[9];
    const float* noise = (const float*)d_in[10];
    const int*   assign_raw = (const int*)d_in[11];

    float* out_obs = (float*)d_out;
    float* out_rew = out_obs + (size_t)B_TOT * T_STEPS * OBS;

    cudaFuncSetAttribute(rollout_kernel,
                         cudaFuncAttributeMaxDynamicSharedMemorySize, SMEM_BYTES);

    setup_kernel<<<1, SETUP_THREADS>>>(assign_raw);
    rollout_kernel<<<MAXTILES, RT_THREADS, SMEM_BYTES>>>(
        obs, acts, W1, b1, W2, b2, W3, b3, maxlv, minlv, noise,
        out_obs, out_rew);
}

// round 10
// speedup vs baseline: 1.9399x; 1.9399x over previous
#include <cuda_runtime.h>
#include <cuda_bf16.h>
#include <math.h>
#include <stdint.h>

// Problem constants
#define B_TOT   4096
#define T_STEPS 25
#define K_ENS   8
#define OBS     64
#define ACT     16
#define IN1     80            // OBS + ACT
#define HID     512
#define OUTD    129           // 2*OBS + 1
#define N3PAD   136           // layer-3 N padded to 17 n8-tiles
#define TM      32            // rows per CTA tile
#define NTHREADS 256          // 8 warps
#define SETUP_THREADS 256
#define MAXTILES 136
#define OUT_STRIDE 132

// activation smem strides (bf16 elems, even, bank-staggered)
#define XS      88            // x: 80 + 8 pad
#define HS      520           // h: 512 + 8 pad

// dynamic smem layout (bytes)
#define OFF_HH   0
#define OFF_HL   (OFF_HH + TM*HS*2)
#define OFF_XH   (OFF_HL + TM*HS*2)
#define OFF_XL   (OFF_XH + TM*XS*2)
#define OFF_OUT  (OFF_XL + TM*XS*2)
#define OFF_B1   (OFF_OUT + TM*OUT_STRIDE*4)
#define OFF_B2   (OFF_B1 + HID*4)
#define OFF_B3   (OFF_B2 + HID*4)
#define SMEM_BYTES (OFF_B3 + N3PAD*4)

// ---- device-global scratch (no allocation allowed) ----
__device__ int g_perm[B_TOT];
__device__ int g_tileK[MAXTILES];
__device__ int g_tileStart[MAXTILES];
__device__ int g_tileRows[MAXTILES];
__device__ int g_ntiles;

// W^T in split bf16: [k_ens][N][K]
__device__ __nv_bfloat16 g_wt1h[K_ENS * HID * IN1];
__device__ __nv_bfloat16 g_wt1l[K_ENS * HID * IN1];
__device__ __nv_bfloat16 g_wt2h[K_ENS * HID * HID];
__device__ __nv_bfloat16 g_wt2l[K_ENS * HID * HID];
__device__ __nv_bfloat16 g_wt3h[K_ENS * N3PAD * HID];
__device__ __nv_bfloat16 g_wt3l[K_ENS * N3PAD * HID];

// ============================================================
// Setup: dtype-detect + counting sort by ensemble + tile meta.
// ============================================================
__global__ void setup_kernel(const int* __restrict__ assign_raw) {
    __shared__ int cnt[K_ENS];
    __shared__ int cur[K_ENS];
    __shared__ int odd_nonzero;
    int tid = threadIdx.x;
    if (tid < K_ENS) cnt[tid] = 0;
    if (tid == 0) odd_nonzero = 0;
    __syncthreads();

    int local_nz = 0;
    for (int w = 2 * tid + 1; w < B_TOT; w += 2 * SETUP_THREADS)
        if (assign_raw[w] != 0) local_nz = 1;
    if (local_nz) atomicOr(&odd_nonzero, 1);
    __syncthreads();
    const bool is_i32 = (odd_nonzero != 0);

    for (int b = tid; b < B_TOT; b += SETUP_THREADS) {
        int k = is_i32 ? assign_raw[b] : assign_raw[2 * b];
        atomicAdd(&cnt[k], 1);
    }
    __syncthreads();
    if (tid == 0) {
        int off = 0, nt = 0;
        for (int k = 0; k < K_ENS; k++) {
            cur[k] = off;
            int c = cnt[k];
            for (int s = 0; s < c; s += TM) {
                g_tileK[nt] = k;
                g_tileStart[nt] = off + s;
                g_tileRows[nt] = (c - s < TM) ? (c - s) : TM;
                nt++;
            }
            off += c;
        }
        g_ntiles = nt;
        for (int e = nt; e < MAXTILES; e++) g_tileRows[e] = 0;
    }
    __syncthreads();
    for (int b = tid; b < B_TOT; b += SETUP_THREADS) {
        int k = is_i32 ? assign_raw[b] : assign_raw[2 * b];
        int pos = atomicAdd(&cur[k], 1);
        g_perm[pos] = b;
    }
}

// ============================================================
// Prep: transpose W [km][R][C] -> WT [km][Cpad][R], split bf16.
// ============================================================
__global__ void prep_transpose(const float* __restrict__ W,
                               __nv_bfloat16* __restrict__ Th,
                               __nv_bfloat16* __restrict__ Tl,
                               int R, int C, int Cpad) {
    __shared__ float tile[32][33];
    int km = blockIdx.z;
    int c0 = blockIdx.x * 32, r0 = blockIdx.y * 32;
    const float* Wm = W + (size_t)km * R * C;
    for (int i = threadIdx.y; i < 32; i += 8) {
        int r = r0 + i, c = c0 + threadIdx.x;
        tile[i][threadIdx.x] = (r < R && c < C) ? Wm[(size_t)r * C + c] : 0.f;
    }
    __syncthreads();
    __nv_bfloat16* Thm = Th + (size_t)km * Cpad * R;
    __nv_bfloat16* Tlm = Tl + (size_t)km * Cpad * R;
    for (int i = threadIdx.y; i < 32; i += 8) {
        int n = c0 + i, k = r0 + threadIdx.x;
        if (n < Cpad && k < R) {
            float v = tile[threadIdx.x][i];
            __nv_bfloat16 h = __float2bfloat16(v);
            Thm[(size_t)n * R + k] = h;
            Tlm[(size_t)n * R + k] = __float2bfloat16(v - __bfloat162float(h));
        }
    }
}

// ============================================================
// Math helpers
// ============================================================
__device__ __forceinline__ float softplusf(float z) {
    return (z > 0.f) ? (z + log1pf(__expf(-z))) : log1pf(__expf(z));
}
__device__ __forceinline__ float swishf(float x) {
    return x * __frcp_rn(1.f + __expf(-x));
}
__device__ __forceinline__ void split_store(__nv_bfloat16* hh, __nv_bfloat16* hl,
                                            int idx, float v) {
    __nv_bfloat16 h = __float2bfloat16(v);
    hh[idx] = h;
    hl[idx] = __float2bfloat16(v - __bfloat162float(h));
}

// mma.sync m16n8k16 bf16 -> fp32
__device__ __forceinline__ void hmma(float& c0, float& c1, float& c2, float& c3,
                                     uint32_t a0, uint32_t a1, uint32_t a2, uint32_t a3,
                                     uint32_t b0, uint32_t b1) {
    asm volatile(
        "mma.sync.aligned.m16n8k16.row.col.f32.bf16.bf16.f32 "
        "{%0,%1,%2,%3}, {%4,%5,%6,%7}, {%8,%9}, {%0,%1,%2,%3};"
        : "+f"(c0), "+f"(c1), "+f"(c2), "+f"(c3)
        : "r"(a0), "r"(a1), "r"(a2), "r"(a3), "r"(b0), "r"(b1));
}

// Load A frags (hi or lo) for both m-tiles at k0 from smem [32][ASTR] bf16.
template<int ASTR>
__device__ __forceinline__ void load_afrag(const __nv_bfloat16* A, int g, int t4, int k0,
                                           uint32_t a[2][4]) {
#pragma unroll
    for (int mt = 0; mt < 2; mt++) {
        const uint32_t* r0p = (const uint32_t*)(A + (mt * 16 + g) * ASTR + k0);
        const uint32_t* r8p = (const uint32_t*)(A + (mt * 16 + g + 8) * ASTR + k0);
        a[mt][0] = r0p[t4];
        a[mt][1] = r8p[t4];
        a[mt][2] = r0p[t4 + 4];
        a[mt][3] = r8p[t4 + 4];
    }
}

// ============================================================
// Persistent rollout: 1 CTA = 32 same-member rows, 25 steps.
// GEMMs on tensor cores (mma.sync bf16, 3-term split).
// ============================================================
__global__ void __launch_bounds__(NTHREADS) rollout_kernel(
    const float* __restrict__ obs,
    const float* __restrict__ acts,
    const float* __restrict__ b1, const float* __restrict__ b2,
    const float* __restrict__ b3,
    const float* __restrict__ maxlv, const float* __restrict__ minlv,
    const float* __restrict__ noise,
    float* __restrict__ out_obs,
    float* __restrict__ out_rew)
{
    const int tile = blockIdx.x;
    if (tile >= g_ntiles) return;
    const int nrows = g_tileRows[tile];
    const int km    = g_tileK[tile];
    const int start = g_tileStart[tile];

    extern __shared__ char sm[];
    __nv_bfloat16* Hh = (__nv_bfloat16*)(sm + OFF_HH);   // [32][HS]
    __nv_bfloat16* Hl = (__nv_bfloat16*)(sm + OFF_HL);
    __nv_bfloat16* Xh = (__nv_bfloat16*)(sm + OFF_XH);   // [32][XS]
    __nv_bfloat16* Xl = (__nv_bfloat16*)(sm + OFF_XL);
    float* sh_out = (float*)(sm + OFF_OUT);              // [32][132]
    float* sb1 = (float*)(sm + OFF_B1);
    float* sb2 = (float*)(sm + OFF_B2);
    float* sb3 = (float*)(sm + OFF_B3);
    __shared__ int rows[TM];

    const int tid  = threadIdx.x;
    const int warp = tid >> 5, lane = tid & 31;
    const int g = lane >> 2, t4 = lane & 3;

    if (tid < TM) rows[tid] = (tid < nrows) ? g_perm[start + tid] : 0;

    // biases to smem
    for (int i = tid; i < HID; i += NTHREADS) {
        sb1[i] = b1[(size_t)km * HID + i];
        sb2[i] = b2[(size_t)km * HID + i];
    }
    for (int i = tid; i < N3PAD; i += NTHREADS)
        sb3[i] = (i < OUTD) ? b3[(size_t)km * OUTD + i] : 0.f;

    const __nv_bfloat16* W1h = g_wt1h + (size_t)km * HID * IN1;
    const __nv_bfloat16* W1l = g_wt1l + (size_t)km * HID * IN1;
    const __nv_bfloat16* W2h = g_wt2h + (size_t)km * HID * HID;
    const __nv_bfloat16* W2l = g_wt2l + (size_t)km * HID * HID;
    const __nv_bfloat16* W3h = g_wt3h + (size_t)km * N3PAD * HID;
    const __nv_bfloat16* W3l = g_wt3l + (size_t)km * N3PAD * HID;

    __syncthreads();

    // init x buffers: zero all, then obs for active rows
    for (int i = tid; i < TM * XS; i += NTHREADS) {
        Xh[i] = __float2bfloat16(0.f);
        Xl[i] = __float2bfloat16(0.f);
    }
    __syncthreads();
    for (int idx = tid; idx < TM * OBS; idx += NTHREADS) {
        int r = idx >> 6, d = idx & 63;
        float v = (r < nrows) ? obs[(size_t)rows[r] * OBS + d] : 0.f;
        split_store(Xh, Xl, r * XS + d, v);
    }

    for (int t = 0; t < T_STEPS; t++) {
        // actions for this step
        for (int idx = tid; idx < TM * ACT; idx += NTHREADS) {
            int r = idx >> 4, a = idx & 15;
            float v = (r < nrows) ? acts[((size_t)rows[r] * T_STEPS + t) * ACT + a] : 0.f;
            split_store(Xh, Xl, r * XS + OBS + a, v);
        }
        __syncthreads();

        // ===== layer 1: x[32,80] @ W1 -> h[32,512] =====
        {
            float acc[16][4];
#pragma unroll
            for (int i = 0; i < 16; i++)
#pragma unroll
                for (int j = 0; j < 4; j++) acc[i][j] = 0.f;

            const int nbase = warp * 64;
#pragma unroll
            for (int kit = 0; kit < IN1 / 16; kit++) {
                int k0 = kit * 16;
                uint32_t ah[2][4], al[2][4];
                load_afrag<XS>(Xh, g, t4, k0, ah);
                load_afrag<XS>(Xl, g, t4, k0, al);
#pragma unroll
                for (int nt = 0; nt < 8; nt++) {
                    int n = nbase + nt * 8 + g;
                    const uint32_t* bh = (const uint32_t*)(W1h + (size_t)n * IN1 + k0);
                    const uint32_t* bl = (const uint32_t*)(W1l + (size_t)n * IN1 + k0);
                    uint32_t bh0 = __ldg(bh + t4), bh1 = __ldg(bh + t4 + 4);
                    uint32_t bl0 = __ldg(bl + t4), bl1 = __ldg(bl + t4 + 4);
#pragma unroll
                    for (int mt = 0; mt < 2; mt++) {
                        float* c = acc[mt * 8 + nt];
                        hmma(c[0], c[1], c[2], c[3], ah[mt][0], ah[mt][1], ah[mt][2], ah[mt][3], bh0, bh1);
                        hmma(c[0], c[1], c[2], c[3], al[mt][0], al[mt][1], al[mt][2], al[mt][3], bh0, bh1);
                        hmma(c[0], c[1], c[2], c[3], ah[mt][0], ah[mt][1], ah[mt][2], ah[mt][3], bl0, bl1);
                    }
                }
            }
            __syncthreads();   // x reads done before h writes? (h != x, but keep layer order clean)
#pragma unroll
            for (int nt = 0; nt < 8; nt++)
#pragma unroll
                for (int mt = 0; mt < 2; mt++) {
                    float* c = acc[mt * 8 + nt];
                    int c0 = nbase + nt * 8 + t4 * 2;
                    int r0 = mt * 16 + g;
                    float bv0 = sb1[c0], bv1 = sb1[c0 + 1];
                    split_store(Hh, Hl, r0 * HS + c0,           swishf(c[0] + bv0));
                    split_store(Hh, Hl, r0 * HS + c0 + 1,       swishf(c[1] + bv1));
                    split_store(Hh, Hl, (r0 + 8) * HS + c0,     swishf(c[2] + bv0));
                    split_store(Hh, Hl, (r0 + 8) * HS + c0 + 1, swishf(c[3] + bv1));
                }
        }
        __syncthreads();

        // ===== layer 2: h[32,512] @ W2 -> h[32,512] (in-place after sync) =====
        {
            float acc[16][4];
#pragma unroll
            for (int i = 0; i < 16; i++)
#pragma unroll
                for (int j = 0; j < 4; j++) acc[i][j] = 0.f;

            const int nbase = warp * 64;
#pragma unroll 2
            for (int kit = 0; kit < HID / 16; kit++) {
                int k0 = kit * 16;
                uint32_t ah[2][4], al[2][4];
                load_afrag<HS>(Hh, g, t4, k0, ah);
                load_afrag<HS>(Hl, g, t4, k0, al);
#pragma unroll
                for (int nt = 0; nt < 8; nt++) {
                    int n = nbase + nt * 8 + g;
                    const uint32_t* bh = (const uint32_t*)(W2h + (size_t)n * HID + k0);
                    const uint32_t* bl = (const uint32_t*)(W2l + (size_t)n * HID + k0);
                    uint32_t bh0 = __ldg(bh + t4), bh1 = __ldg(bh + t4 + 4);
                    uint32_t bl0 = __ldg(bl + t4), bl1 = __ldg(bl + t4 + 4);
#pragma unroll
                    for (int mt = 0; mt < 2; mt++) {
                        float* c = acc[mt * 8 + nt];
                        hmma(c[0], c[1], c[2], c[3], ah[mt][0], ah[mt][1], ah[mt][2], ah[mt][3], bh0, bh1);
                        hmma(c[0], c[1], c[2], c[3], al[mt][0], al[mt][1], al[mt][2], al[mt][3], bh0, bh1);
                        hmma(c[0], c[1], c[2], c[3], ah[mt][0], ah[mt][1], ah[mt][2], ah[mt][3], bl0, bl1);
                    }
                }
            }
            __syncthreads();   // ALL warps done reading h1 before overwriting with h2
#pragma unroll
            for (int nt = 0; nt < 8; nt++)
#pragma unroll
                for (int mt = 0; mt < 2; mt++) {
                    float* c = acc[mt * 8 + nt];
                    int c0 = nbase + nt * 8 + t4 * 2;
                    int r0 = mt * 16 + g;
                    float bv0 = sb2[c0], bv1 = sb2[c0 + 1];
                    split_store(Hh, Hl, r0 * HS + c0,           swishf(c[0] + bv0));
                    split_store(Hh, Hl, r0 * HS + c0 + 1,       swishf(c[1] + bv1));
                    split_store(Hh, Hl, (r0 + 8) * HS + c0,     swishf(c[2] + bv0));
                    split_store(Hh, Hl, (r0 + 8) * HS + c0 + 1, swishf(c[3] + bv1));
                }
        }
        __syncthreads();

        // ===== layer 3: h[32,512] @ W3 -> out[32,129] =====
        {
            // warp w owns n8-tiles {2w, 2w+1}; warp 0 also tile 16 (cols 128-135)
            float acc[3][2][4];
#pragma unroll
            for (int i = 0; i < 3; i++)
#pragma unroll
                for (int m = 0; m < 2; m++)
#pragma unroll
                    for (int j = 0; j < 4; j++) acc[i][m][j] = 0.f;
            const int nt3 = (warp == 0) ? 3 : 2;
            int tiles[3] = {warp * 2, warp * 2 + 1, 16};

#pragma unroll 2
            for (int kit = 0; kit < HID / 16; kit++) {
                int k0 = kit * 16;
                uint32_t ah[2][4], al[2][4];
                load_afrag<HS>(Hh, g, t4, k0, ah);
                load_afrag<HS>(Hl, g, t4, k0, al);
                for (int i = 0; i < nt3; i++) {
                    int n = tiles[i] * 8 + g;
                    const uint32_t* bh = (const uint32_t*)(W3h + (size_t)n * HID + k0);
                    const uint32_t* bl = (const uint32_t*)(W3l + (size_t)n * HID + k0);
                    uint32_t bh0 = __ldg(bh + t4), bh1 = __ldg(bh + t4 + 4);
                    uint32_t bl0 = __ldg(bl + t4), bl1 = __ldg(bl + t4 + 4);
#pragma unroll
                    for (int mt = 0; mt < 2; mt++) {
                        float* c = acc[i][mt];
                        hmma(c[0], c[1], c[2], c[3], ah[mt][0], ah[mt][1], ah[mt][2], ah[mt][3], bh0, bh1);
                        hmma(c[0], c[1], c[2], c[3], al[mt][0], al[mt][1], al[mt][2], al[mt][3], bh0, bh1);
                        hmma(c[0], c[1], c[2], c[3], ah[mt][0], ah[mt][1], ah[mt][2], ah[mt][3], bl0, bl1);
                    }
                }
            }
            __syncthreads();
            for (int i = 0; i < nt3; i++) {
                int c0 = tiles[i] * 8 + t4 * 2;
#pragma unroll
                for (int mt = 0; mt < 2; mt++) {
                    float* c = acc[i][mt];
                    int r0 = mt * 16 + g;
                    if (c0 < OUT_STRIDE) {
                        sh_out[r0 * OUT_STRIDE + c0]       = c[0] + sb3[c0];
                        sh_out[(r0 + 8) * OUT_STRIDE + c0] = c[2] + sb3[c0];
                    }
                    if (c0 + 1 < OUT_STRIDE) {
                        sh_out[r0 * OUT_STRIDE + c0 + 1]       = c[1] + sb3[c0 + 1];
                        sh_out[(r0 + 8) * OUT_STRIDE + c0 + 1] = c[3] + sb3[c0 + 1];
                    }
                }
            }
        }
        __syncthreads();

        // ===== postprocess =====
        const float* nz_t = noise + ((size_t)t * K_ENS + km) * B_TOT * OBS;
        for (int idx = tid; idx < TM * OBS; idx += NTHREADS) {
            int r = idx >> 6, d = idx & 63;
            if (r < nrows) {
                int row = rows[r];
                float mean = sh_out[r * OUT_STRIDE + d];
                float lv   = sh_out[r * OUT_STRIDE + OBS + d];
                float mx = __ldg(maxlv + d), mn = __ldg(minlv + d);
                lv = mx - softplusf(mx - lv);
                lv = mn + softplusf(lv - mn);
                float nz = __ldg(nz_t + (size_t)row * OBS + d);
                float no = fmaf(nz, __expf(0.5f * lv), mean);
                out_obs[((size_t)row * T_STEPS + t) * OBS + d] = no;
                split_store(Xh, Xl, r * XS + d, no);
            }
        }
        if (tid < nrows)
            out_rew[(size_t)rows[tid] * T_STEPS + t] = sh_out[tid * OUT_STRIDE + 128];
        __syncthreads();
    }
}

// ============================================================
// Launch
// ============================================================
extern "C" void kernel_launch(void* const* d_in, const int* in_sizes, int n_in,
                              void* d_out, int out_size) {
    const float* obs   = (const float*)d_in[0];
    const float* acts  = (const float*)d_in[1];
    const float* W1    = (const float*)d_in[2];
    const float* b1    = (const float*)d_in[3];
    const float* W2    = (const float*)d_in[4];
    const float* b2    = (const float*)d_in[5];
    const float* W3    = (const float*)d_in[6];
    const float* b3    = (const float*)d_in[7];
    const float* maxlv = (const float*)d_in[8];
    const float* minlv = (const float*)d_in[9];
    const float* noise = (const float*)d_in[10];
    const int*   assign_raw = (const int*)d_in[11];

    float* out_obs = (float*)d_out;
    float* out_rew = out_obs + (size_t)B_TOT * T_STEPS * OBS;

    // resolve device-global symbol addresses (host side, not capture-relevant)
    __nv_bfloat16 *wt1h, *wt1l, *wt2h, *wt2l, *wt3h, *wt3l;
    cudaGetSymbolAddress((void**)&wt1h, g_wt1h);
    cudaGetSymbolAddress((void**)&wt1l, g_wt1l);
    cudaGetSymbolAddress((void**)&wt2h, g_wt2h);
    cudaGetSymbolAddress((void**)&wt2l, g_wt2l);
    cudaGetSymbolAddress((void**)&wt3h, g_wt3h);
    cudaGetSymbolAddress((void**)&wt3l, g_wt3l);

    cudaFuncSetAttribute(rollout_kernel,
                         cudaFuncAttributeMaxDynamicSharedMemorySize, SMEM_BYTES);

    setup_kernel<<<1, SETUP_THREADS>>>(assign_raw);

    dim3 blk(32, 8);
    prep_transpose<<<dim3(16, 3, K_ENS), blk>>>(W1, wt1h, wt1l, IN1, HID, HID);
    prep_transpose<<<dim3(16, 16, K_ENS), blk>>>(W2, wt2h, wt2l, HID, HID, HID);
    prep_transpose<<<dim3(5, 16, K_ENS), blk>>>(W3, wt3h, wt3l, HID, OUTD, N3PAD);

    rollout_kernel<<<MAXTILES, NTHREADS, SMEM_BYTES>>>(
        obs, acts, b1, b2, b3, maxlv, minlv, noise, out_obs, out_rew);
}

// round 11
// speedup vs baseline: 1.9992x; 1.0306x over previous
#include <cuda_runtime.h>
#include <cuda_bf16.h>
#include <math.h>
#include <stdint.h>

// Problem constants
#define B_TOT   4096
#define T_STEPS 25
#define K_ENS   8
#define OBS     64
#define ACT     16
#define IN1     80
#define HID     512
#define OUTD    129
#define N3PAD   136
#define TM      32
#define NTHREADS 512          // 16 warps
#define SETUP_THREADS 256
#define MAXTILES 136
#define OUT_STRIDE 132

// activation smem strides (bf16 elems)
#define XS      88            // 176 B/row: conflict-free for LDSM (mod 128 distinct)
#define HS      520           // 1040 B/row: conflict-free for LDSM

// dynamic smem layout (bytes)
#define OFF_HH   0
#define OFF_HL   (OFF_HH + TM*HS*2)
#define OFF_XH   (OFF_HL + TM*HS*2)
#define OFF_XL   (OFF_XH + TM*XS*2)
#define OFF_OUT  (OFF_XL + TM*XS*2)
#define OFF_B1   (OFF_OUT + TM*OUT_STRIDE*4)
#define OFF_B2   (OFF_B1 + HID*4)
#define OFF_B3   (OFF_B2 + HID*4)
#define SMEM_BYTES (OFF_B3 + N3PAD*4)

// ---- device-global scratch ----
__device__ int g_perm[B_TOT];
__device__ int g_tileK[MAXTILES];
__device__ int g_tileStart[MAXTILES];
__device__ int g_tileRows[MAXTILES];
__device__ int g_ntiles;

// W^T split bf16: [k_ens][N][K]
__device__ __nv_bfloat16 g_wt1h[K_ENS * HID * IN1];
__device__ __nv_bfloat16 g_wt1l[K_ENS * HID * IN1];
__device__ __nv_bfloat16 g_wt2h[K_ENS * HID * HID];
__device__ __nv_bfloat16 g_wt2l[K_ENS * HID * HID];
__device__ __nv_bfloat16 g_wt3h[K_ENS * N3PAD * HID];
__device__ __nv_bfloat16 g_wt3l[K_ENS * N3PAD * HID];

// ============================================================
// Setup kernel
// ============================================================
__global__ void setup_kernel(const int* __restrict__ assign_raw) {
    __shared__ int cnt[K_ENS];
    __shared__ int cur[K_ENS];
    __shared__ int odd_nonzero;
    int tid = threadIdx.x;
    if (tid < K_ENS) cnt[tid] = 0;
    if (tid == 0) odd_nonzero = 0;
    __syncthreads();

    int local_nz = 0;
    for (int w = 2 * tid + 1; w < B_TOT; w += 2 * SETUP_THREADS)
        if (assign_raw[w] != 0) local_nz = 1;
    if (local_nz) atomicOr(&odd_nonzero, 1);
    __syncthreads();
    const bool is_i32 = (odd_nonzero != 0);

    for (int b = tid; b < B_TOT; b += SETUP_THREADS) {
        int k = is_i32 ? assign_raw[b] : assign_raw[2 * b];
        atomicAdd(&cnt[k], 1);
    }
    __syncthreads();
    if (tid == 0) {
        int off = 0, nt = 0;
        for (int k = 0; k < K_ENS; k++) {
            cur[k] = off;
            int c = cnt[k];
            for (int s = 0; s < c; s += TM) {
                g_tileK[nt] = k;
                g_tileStart[nt] = off + s;
                g_tileRows[nt] = (c - s < TM) ? (c - s) : TM;
                nt++;
            }
            off += c;
        }
        g_ntiles = nt;
        for (int e = nt; e < MAXTILES; e++) g_tileRows[e] = 0;
    }
    __syncthreads();
    for (int b = tid; b < B_TOT; b += SETUP_THREADS) {
        int k = is_i32 ? assign_raw[b] : assign_raw[2 * b];
        int pos = atomicAdd(&cur[k], 1);
        g_perm[pos] = b;
    }
}

// ============================================================
// Prep: transpose + split
// ============================================================
__global__ void prep_transpose(const float* __restrict__ W,
                               __nv_bfloat16* __restrict__ Th,
                               __nv_bfloat16* __restrict__ Tl,
                               int R, int C, int Cpad) {
    __shared__ float tile[32][33];
    int km = blockIdx.z;
    int c0 = blockIdx.x * 32, r0 = blockIdx.y * 32;
    const float* Wm = W + (size_t)km * R * C;
    for (int i = threadIdx.y; i < 32; i += 8) {
        int r = r0 + i, c = c0 + threadIdx.x;
        tile[i][threadIdx.x] = (r < R && c < C) ? Wm[(size_t)r * C + c] : 0.f;
    }
    __syncthreads();
    __nv_bfloat16* Thm = Th + (size_t)km * Cpad * R;
    __nv_bfloat16* Tlm = Tl + (size_t)km * Cpad * R;
    for (int i = threadIdx.y; i < 32; i += 8) {
        int n = c0 + i, k = r0 + threadIdx.x;
        if (n < Cpad && k < R) {
            float v = tile[threadIdx.x][i];
            __nv_bfloat16 h = __float2bfloat16(v);
            Thm[(size_t)n * R + k] = h;
            Tlm[(size_t)n * R + k] = __float2bfloat16(v - __bfloat162float(h));
        }
    }
}

// ============================================================
// Helpers
// ============================================================
__device__ __forceinline__ float softplusf(float z) {
    return (z > 0.f) ? (z + log1pf(__expf(-z))) : log1pf(__expf(z));
}
__device__ __forceinline__ float swishf(float x) {
    return x * __frcp_rn(1.f + __expf(-x));
}
__device__ __forceinline__ void split_store(__nv_bfloat16* hh, __nv_bfloat16* hl,
                                            int idx, float v) {
    __nv_bfloat16 h = __float2bfloat16(v);
    hh[idx] = h;
    hl[idx] = __float2bfloat16(v - __bfloat162float(h));
}
__device__ __forceinline__ uint32_t smem_u32(const void* p) {
    uint32_t a;
    asm("{ .reg .u64 t; cvta.to.shared.u64 t, %1; cvt.u32.u64 %0, t; }" : "=r"(a) : "l"(p));
    return a;
}

// mma.sync m16n8k16 bf16 -> fp32 (NOT volatile: let ptxas schedule)
__device__ __forceinline__ void hmma(float* c, const uint32_t* a,
                                     uint32_t b0, uint32_t b1) {
    asm("mma.sync.aligned.m16n8k16.row.col.f32.bf16.bf16.f32 "
        "{%0,%1,%2,%3}, {%4,%5,%6,%7}, {%8,%9}, {%0,%1,%2,%3};"
        : "+f"(c[0]), "+f"(c[1]), "+f"(c[2]), "+f"(c[3])
        : "r"(a[0]), "r"(a[1]), "r"(a[2]), "r"(a[3]), "r"(b0), "r"(b1));
}

// ldmatrix x4 b16 (row-major A fragment)
__device__ __forceinline__ void ldsm_x4(uint32_t* a, uint32_t addr) {
    asm volatile("ldmatrix.sync.aligned.m8n8.x4.shared.b16 {%0,%1,%2,%3}, [%4];"
        : "=r"(a[0]), "=r"(a[1]), "=r"(a[2]), "=r"(a[3]) : "r"(addr));
}

// ============================================================
// Dense layer (layers 1 & 2): O = swish(A @ W^T + bias)
// 16 warps, each owns 32 cols (4 n8-tiles) x 32 rows (2 m16).
// Term-major hmma order breaks accumulation chains.
// ============================================================
template<int KDIM, int ASTR>
__device__ __forceinline__ void layer_dense(
    const __nv_bfloat16* Ah, const __nv_bfloat16* Al,
    const __nv_bfloat16* __restrict__ Wh, const __nv_bfloat16* __restrict__ Wl,
    const float* bias,
    __nv_bfloat16* Oh, __nv_bfloat16* Ol,
    int warp, int lane)
{
    const int g = lane >> 2, t4 = lane & 3;
    const int nbase = warp * 32;

    float acc[8][4];
#pragma unroll
    for (int i = 0; i < 8; i++)
#pragma unroll
        for (int j = 0; j < 4; j++) acc[i][j] = 0.f;

    // per-lane LDSM row addresses (bytes), k0 added per iter
    const uint32_t aAh = smem_u32(Ah), aAl = smem_u32(Al);
    const int roff0 = (((lane & 15)) * ASTR + ((lane >> 4) * 8)) * 2;
    const int roff1 = (((lane & 15) + 16) * ASTR + ((lane >> 4) * 8)) * 2;

#pragma unroll 2
    for (int kit = 0; kit < KDIM / 16; kit++) {
        const int k0 = kit * 16, kb = k0 * 2;
        uint32_t ah[2][4], al[2][4];
        ldsm_x4(ah[0], aAh + roff0 + kb);
        ldsm_x4(ah[1], aAh + roff1 + kb);
        ldsm_x4(al[0], aAl + roff0 + kb);
        ldsm_x4(al[1], aAl + roff1 + kb);

        uint32_t bh[4][2], bl[4][2];
#pragma unroll
        for (int nt = 0; nt < 4; nt++) {
            const int n = nbase + nt * 8 + g;
            const uint32_t* ph = (const uint32_t*)(Wh + (size_t)n * KDIM + k0);
            const uint32_t* pl = (const uint32_t*)(Wl + (size_t)n * KDIM + k0);
            bh[nt][0] = __ldg(ph + t4); bh[nt][1] = __ldg(ph + t4 + 4);
            bl[nt][0] = __ldg(pl + t4); bl[nt][1] = __ldg(pl + t4 + 4);
        }
        // term 1: Ah * Wh
#pragma unroll
        for (int nt = 0; nt < 4; nt++)
#pragma unroll
            for (int mt = 0; mt < 2; mt++)
                hmma(acc[nt * 2 + mt], ah[mt], bh[nt][0], bh[nt][1]);
        // term 2: Al * Wh
#pragma unroll
        for (int nt = 0; nt < 4; nt++)
#pragma unroll
            for (int mt = 0; mt < 2; mt++)
                hmma(acc[nt * 2 + mt], al[mt], bh[nt][0], bh[nt][1]);
        // term 3: Ah * Wl
#pragma unroll
        for (int nt = 0; nt < 4; nt++)
#pragma unroll
            for (int mt = 0; mt < 2; mt++)
                hmma(acc[nt * 2 + mt], ah[mt], bl[nt][0], bl[nt][1]);
    }
    __syncthreads();   // all reads of input activations complete before overwrite
#pragma unroll
    for (int nt = 0; nt < 4; nt++)
#pragma unroll
        for (int mt = 0; mt < 2; mt++) {
            float* c = acc[nt * 2 + mt];
            const int c0 = nbase + nt * 8 + t4 * 2;
            const int r0 = mt * 16 + g;
            const float bv0 = bias[c0], bv1 = bias[c0 + 1];
            split_store(Oh, Ol, r0 * HS + c0,           swishf(c[0] + bv0));
            split_store(Oh, Ol, r0 * HS + c0 + 1,       swishf(c[1] + bv1));
            split_store(Oh, Ol, (r0 + 8) * HS + c0,     swishf(c[2] + bv0));
            split_store(Oh, Ol, (r0 + 8) * HS + c0 + 1, swishf(c[3] + bv1));
        }
}

// ============================================================
// Persistent rollout
// ============================================================
__global__ void __launch_bounds__(NTHREADS) rollout_kernel(
    const float* __restrict__ obs,
    const float* __restrict__ acts,
    const float* __restrict__ b1, const float* __restrict__ b2,
    const float* __restrict__ b3,
    const float* __restrict__ maxlv, const float* __restrict__ minlv,
    const float* __restrict__ noise,
    float* __restrict__ out_obs,
    float* __restrict__ out_rew)
{
    const int tile = blockIdx.x;
    if (tile >= g_ntiles) return;
    const int nrows = g_tileRows[tile];
    const int km    = g_tileK[tile];
    const int start = g_tileStart[tile];

    extern __shared__ char sm[];
    __nv_bfloat16* Hh = (__nv_bfloat16*)(sm + OFF_HH);
    __nv_bfloat16* Hl = (__nv_bfloat16*)(sm + OFF_HL);
    __nv_bfloat16* Xh = (__nv_bfloat16*)(sm + OFF_XH);
    __nv_bfloat16* Xl = (__nv_bfloat16*)(sm + OFF_XL);
    float* sh_out = (float*)(sm + OFF_OUT);
    float* sb1 = (float*)(sm + OFF_B1);
    float* sb2 = (float*)(sm + OFF_B2);
    float* sb3 = (float*)(sm + OFF_B3);
    __shared__ int rows[TM];

    const int tid  = threadIdx.x;
    const int warp = tid >> 5, lane = tid & 31;
    const int g = lane >> 2, t4 = lane & 3;

    if (tid < TM) rows[tid] = (tid < nrows) ? g_perm[start + tid] : 0;

    for (int i = tid; i < HID; i += NTHREADS) {
        sb1[i] = b1[(size_t)km * HID + i];
        sb2[i] = b2[(size_t)km * HID + i];
    }
    for (int i = tid; i < N3PAD; i += NTHREADS)
        sb3[i] = (i < OUTD) ? b3[(size_t)km * OUTD + i] : 0.f;

    const __nv_bfloat16* W1h = g_wt1h + (size_t)km * HID * IN1;
    const __nv_bfloat16* W1l = g_wt1l + (size_t)km * HID * IN1;
    const __nv_bfloat16* W2h = g_wt2h + (size_t)km * HID * HID;
    const __nv_bfloat16* W2l = g_wt2l + (size_t)km * HID * HID;
    const __nv_bfloat16* W3h = g_wt3h + (size_t)km * N3PAD * HID;
    const __nv_bfloat16* W3l = g_wt3l + (size_t)km * N3PAD * HID;

    __syncthreads();

    for (int i = tid; i < TM * XS; i += NTHREADS) {
        Xh[i] = __float2bfloat16(0.f);
        Xl[i] = __float2bfloat16(0.f);
    }
    __syncthreads();
    for (int idx = tid; idx < TM * OBS; idx += NTHREADS) {
        int r = idx >> 6, d = idx & 63;
        float v = (r < nrows) ? obs[(size_t)rows[r] * OBS + d] : 0.f;
        split_store(Xh, Xl, r * XS + d, v);
    }

    for (int t = 0; t < T_STEPS; t++) {
        for (int idx = tid; idx < TM * ACT; idx += NTHREADS) {
            int r = idx >> 4, a = idx & 15;
            float v = (r < nrows) ? acts[((size_t)rows[r] * T_STEPS + t) * ACT + a] : 0.f;
            split_store(Xh, Xl, r * XS + OBS + a, v);
        }
        __syncthreads();

        // layer 1: x[32,80] -> h[32,512]
        layer_dense<IN1, XS>(Xh, Xl, W1h, W1l, sb1, Hh, Hl, warp, lane);
        __syncthreads();
        // layer 2: h -> h (in-place safe: sync inside after reads)
        layer_dense<HID, HS>(Hh, Hl, W2h, W2l, sb2, Hh, Hl, warp, lane);
        __syncthreads();

        // ===== layer 3: h[32,512] @ W3 -> out[32,129] =====
        {
            // warp w owns n8-tile w; warp 0 also tile 16 (cols 128-135)
            float acc[2][2][4];
#pragma unroll
            for (int i = 0; i < 2; i++)
#pragma unroll
                for (int m = 0; m < 2; m++)
#pragma unroll
                    for (int j = 0; j < 4; j++) acc[i][m][j] = 0.f;
            const int ntiles = (warp == 0) ? 2 : 1;
            const int tn[2] = {warp, 16};

            const uint32_t aHh = smem_u32(Hh), aHl = smem_u32(Hl);
            const int roff0 = (((lane & 15)) * HS + ((lane >> 4) * 8)) * 2;
            const int roff1 = (((lane & 15) + 16) * HS + ((lane >> 4) * 8)) * 2;

#pragma unroll 2
            for (int kit = 0; kit < HID / 16; kit++) {
                const int k0 = kit * 16, kb = k0 * 2;
                uint32_t ah[2][4], al[2][4];
                ldsm_x4(ah[0], aHh + roff0 + kb);
                ldsm_x4(ah[1], aHh + roff1 + kb);
                ldsm_x4(al[0], aHl + roff0 + kb);
                ldsm_x4(al[1], aHl + roff1 + kb);

                uint32_t bh[2][2], bl[2][2];
#pragma unroll
                for (int i = 0; i < 2; i++) {
                    if (i < ntiles) {
                        const int n = tn[i] * 8 + g;
                        const uint32_t* ph = (const uint32_t*)(W3h + (size_t)n * HID + k0);
                        const uint32_t* pl = (const uint32_t*)(W3l + (size_t)n * HID + k0);
                        bh[i][0] = __ldg(ph + t4); bh[i][1] = __ldg(ph + t4 + 4);
                        bl[i][0] = __ldg(pl + t4); bl[i][1] = __ldg(pl + t4 + 4);
                    }
                }
#pragma unroll
                for (int i = 0; i < 2; i++)
                    if (i < ntiles)
#pragma unroll
                        for (int mt = 0; mt < 2; mt++)
                            hmma(acc[i][mt], ah[mt], bh[i][0], bh[i][1]);
#pragma unroll
                for (int i = 0; i < 2; i++)
                    if (i < ntiles)
#pragma unroll
                        for (int mt = 0; mt < 2; mt++)
                            hmma(acc[i][mt], al[mt], bh[i][0], bh[i][1]);
#pragma unroll
                for (int i = 0; i < 2; i++)
                    if (i < ntiles)
#pragma unroll
                        for (int mt = 0; mt < 2; mt++)
                            hmma(acc[i][mt], ah[mt], bl[i][0], bl[i][1]);
            }
            __syncthreads();
            for (int i = 0; i < ntiles; i++) {
                const int c0 = tn[i] * 8 + t4 * 2;
#pragma unroll
                for (int mt = 0; mt < 2; mt++) {
                    float* c = acc[i][mt];
                    const int r0 = mt * 16 + g;
                    if (c0 < OUT_STRIDE) {
                        sh_out[r0 * OUT_STRIDE + c0]       = c[0] + sb3[c0];
                        sh_out[(r0 + 8) * OUT_STRIDE + c0] = c[2] + sb3[c0];
                    }
                    if (c0 + 1 < OUT_STRIDE) {
                        sh_out[r0 * OUT_STRIDE + c0 + 1]       = c[1] + sb3[c0 + 1];
                        sh_out[(r0 + 8) * OUT_STRIDE + c0 + 1] = c[3] + sb3[c0 + 1];
                    }
                }
            }
        }
        __syncthreads();

        // ===== postprocess =====
        const float* nz_t = noise + ((size_t)t * K_ENS + km) * B_TOT * OBS;
        for (int idx = tid; idx < TM * OBS; idx += NTHREADS) {
            int r = idx >> 6, d = idx & 63;
            if (r < nrows) {
                int row = rows[r];
                float mean = sh_out[r * OUT_STRIDE + d];
                float lv   = sh_out[r * OUT_STRIDE + OBS + d];
                float mx = __ldg(maxlv + d), mn = __ldg(minlv + d);
                lv = mx - softplusf(mx - lv);
                lv = mn + softplusf(lv - mn);
                float nz = __ldg(nz_t + (size_t)row * OBS + d);
                float no = fmaf(nz, __expf(0.5f * lv), mean);
                out_obs[((size_t)row * T_STEPS + t) * OBS + d] = no;
                split_store(Xh, Xl, r * XS + d, no);
            }
        }
        if (tid < nrows)
            out_rew[(size_t)rows[tid] * T_STEPS + t] = sh_out[tid * OUT_STRIDE + 128];
        __syncthreads();
    }
}

// ============================================================
// Launch
// ============================================================
extern "C" void kernel_launch(void* const* d_in, const int* in_sizes, int n_in,
                              void* d_out, int out_size) {
    const float* obs   = (const float*)d_in[0];
    const float* acts  = (const float*)d_in[1];
    const float* W1    = (const float*)d_in[2];
    const float* b1    = (const float*)d_in[3];
    const float* W2    = (const float*)d_in[4];
    const float* b2    = (const float*)d_in[5];
    const float* W3    = (const float*)d_in[6];
    const float* b3    = (const float*)d_in[7];
    const float* maxlv = (const float*)d_in[8];
    const float* minlv = (const float*)d_in[9];
    const float* noise = (const float*)d_in[10];
    const int*   assign_raw = (const int*)d_in[11];

    float* out_obs = (float*)d_out;
    float* out_rew = out_obs + (size_t)B_TOT * T_STEPS * OBS;

    __nv_bfloat16 *wt1h, *wt1l, *wt2h, *wt2l, *wt3h, *wt3l;
    cudaGetSymbolAddress((void**)&wt1h, g_wt1h);
    cudaGetSymbolAddress((void**)&wt1l, g_wt1l);
    cudaGetSymbolAddress((void**)&wt2h, g_wt2h);
    cudaGetSymbolAddress((void**)&wt2l, g_wt2l);
    cudaGetSymbolAddress((void**)&wt3h, g_wt3h);
    cudaGetSymbolAddress((void**)&wt3l, g_wt3l);

    cudaFuncSetAttribute(rollout_kernel,
                         cudaFuncAttributeMaxDynamicSharedMemorySize, SMEM_BYTES);

    setup_kernel<<<1, SETUP_THREADS>>>(assign_raw);

    dim3 blk(32, 8);
    prep_transpose<<<dim3(16, 3, K_ENS), blk>>>(W1, wt1h, wt1l, IN1, HID, HID);
    prep_transpose<<<dim3(16, 16, K_ENS), blk>>>(W2, wt2h, wt2l, HID, HID, HID);
    prep_transpose<<<dim3(5, 16, K_ENS), blk>>>(W3, wt3h, wt3l, HID, OUTD, N3PAD);

    rollout_kernel<<<MAXTILES, NTHREADS, SMEM_BYTES>>>(
        obs, acts, b1, b2, b3, maxlv, minlv, noise, out_obs, out_rew);
}

// round 12
// speedup vs baseline: 3.8196x; 1.9106x over previous
#include <cuda_runtime.h>
#include <cuda_bf16.h>
#include <math.h>
#include <stdint.h>

// Problem constants
#define B_TOT   4096
#define T_STEPS 25
#define K_ENS   8
#define OBS     64
#define ACT     16
#define IN1     80
#define HID     512
#define OUTD    129
#define N3PAD   136
#define TM      32
#define NTHREADS 512          // 16 warps
#define SETUP_THREADS 256
#define MAXTILES 136
#define OUT_STRIDE 132

// kit counts
#define NKIT1   (IN1/16)      // 5
#define NKIT2   (HID/16)      // 32
#define NKIT3   (HID/16)      // 32
#define NT1     (HID/8)       // 64 n8-tiles
#define NT3     (N3PAD/8)     // 17

// activation smem strides (bf16 elems)
#define XS      88
#define HS      520

// dynamic smem layout (bytes)
#define OFF_HH   0
#define OFF_HL   (OFF_HH + TM*HS*2)
#define OFF_XH   (OFF_HL + TM*HS*2)
#define OFF_XL   (OFF_XH + TM*XS*2)
#define OFF_OUT  (OFF_XL + TM*XS*2)
#define OFF_B1   (OFF_OUT + TM*OUT_STRIDE*4)
#define OFF_B2   (OFF_B1 + HID*4)
#define OFF_B3   (OFF_B2 + HID*4)
#define SMEM_BYTES (OFF_B3 + N3PAD*4)

// ---- device-global scratch ----
__device__ int g_perm[B_TOT];
__device__ int g_tileK[MAXTILES];
__device__ int g_tileStart[MAXTILES];
__device__ int g_tileRows[MAXTILES];
__device__ int g_ntiles;

// fragment-packed weights: [km][n8][kit][lane] -> {bh0,bh1,bl0,bl1}
__device__ uint4 g_wp1[K_ENS * NT1 * NKIT1 * 32];
__device__ uint4 g_wp2[K_ENS * NT1 * NKIT2 * 32];
__device__ uint4 g_wp3[K_ENS * NT3 * NKIT3 * 32];

// ============================================================
// Setup kernel
// ============================================================
__global__ void setup_kernel(const int* __restrict__ assign_raw) {
    __shared__ int cnt[K_ENS];
    __shared__ int cur[K_ENS];
    __shared__ int odd_nonzero;
    int tid = threadIdx.x;
    if (tid < K_ENS) cnt[tid] = 0;
    if (tid == 0) odd_nonzero = 0;
    __syncthreads();

    int local_nz = 0;
    for (int w = 2 * tid + 1; w < B_TOT; w += 2 * SETUP_THREADS)
        if (assign_raw[w] != 0) local_nz = 1;
    if (local_nz) atomicOr(&odd_nonzero, 1);
    __syncthreads();
    const bool is_i32 = (odd_nonzero != 0);

    for (int b = tid; b < B_TOT; b += SETUP_THREADS) {
        int k = is_i32 ? assign_raw[b] : assign_raw[2 * b];
        atomicAdd(&cnt[k], 1);
    }
    __syncthreads();
    if (tid == 0) {
        int off = 0, nt = 0;
        for (int k = 0; k < K_ENS; k++) {
            cur[k] = off;
            int c = cnt[k];
            for (int s = 0; s < c; s += TM) {
                g_tileK[nt] = k;
                g_tileStart[nt] = off + s;
                g_tileRows[nt] = (c - s < TM) ? (c - s) : TM;
                nt++;
            }
            off += c;
        }
        g_ntiles = nt;
        for (int e = nt; e < MAXTILES; e++) g_tileRows[e] = 0;
    }
    __syncthreads();
    for (int b = tid; b < B_TOT; b += SETUP_THREADS) {
        int k = is_i32 ? assign_raw[b] : assign_raw[2 * b];
        int pos = atomicAdd(&cur[k], 1);
        g_perm[pos] = b;
    }
}

// ============================================================
// Prep: pack W [km][K][N] (float, row-major) into fragment-ready
// uint4 layout [km][n8][kit][lane] = {bh0,bh1,bl0,bl1}.
// b0 covers k = kit*16 + 2*t4 (+1); b1 covers k = kit*16+8+2*t4 (+1).
// n = tile*8 + (lane>>2). Cols >= N are zero.
// ============================================================
__device__ __forceinline__ uint32_t pack_hi(float v0, float v1) {
    __nv_bfloat162 p = __floats2bfloat162_rn(v0, v1);
    return *(uint32_t*)&p;
}
__global__ void pack_frags(const float* __restrict__ W, uint4* __restrict__ out,
                           int K, int N, int NP) {
    const int km = blockIdx.z;
    const int nkit = K / 16, ntile = NP / 8;
    const int total = ntile * nkit * 32;
    int idx = blockIdx.x * blockDim.x + threadIdx.x;
    if (idx >= total) return;

    const int lane = idx & 31;
    const int kit  = (idx >> 5) % nkit;
    const int tile = (idx >> 5) / nkit;
    const int g = lane >> 2, t4 = lane & 3;
    const int n = tile * 8 + g;
    const int ka = kit * 16 + 2 * t4;       // b0: k=ka, ka+1
    const int kb = kit * 16 + 8 + 2 * t4;   // b1: k=kb, kb+1

    const float* Wm = W + (size_t)km * K * N;
    float va0 = (n < N) ? Wm[(size_t)ka * N + n] : 0.f;
    float va1 = (n < N) ? Wm[(size_t)(ka + 1) * N + n] : 0.f;
    float vb0 = (n < N) ? Wm[(size_t)kb * N + n] : 0.f;
    float vb1 = (n < N) ? Wm[(size_t)(kb + 1) * N + n] : 0.f;

    // hi parts
    __nv_bfloat16 ha0 = __float2bfloat16(va0), ha1 = __float2bfloat16(va1);
    __nv_bfloat16 hb0 = __float2bfloat16(vb0), hb1 = __float2bfloat16(vb1);
    // lo residuals
    float la0 = va0 - __bfloat162float(ha0), la1 = va1 - __bfloat162float(ha1);
    float lb0 = vb0 - __bfloat162float(hb0), lb1 = vb1 - __bfloat162float(hb1);

    uint4 v;
    v.x = ((uint32_t)*(uint16_t*)&ha0) | ((uint32_t)*(uint16_t*)&ha1 << 16);
    v.y = ((uint32_t)*(uint16_t*)&hb0) | ((uint32_t)*(uint16_t*)&hb1 << 16);
    v.z = pack_hi(la0, la1);
    v.w = pack_hi(lb0, lb1);

    out[(size_t)km * total + ((size_t)tile * nkit + kit) * 32 + lane] = v;
}

// ============================================================
// Helpers
// ============================================================
__device__ __forceinline__ float softplusf(float z) {
    return (z > 0.f) ? (z + log1pf(__expf(-z))) : log1pf(__expf(z));
}
__device__ __forceinline__ float swishf(float x) {
    return x * __frcp_rn(1.f + __expf(-x));
}
__device__ __forceinline__ void split_store(__nv_bfloat16* hh, __nv_bfloat16* hl,
                                            int idx, float v) {
    __nv_bfloat16 h = __float2bfloat16(v);
    hh[idx] = h;
    hl[idx] = __float2bfloat16(v - __bfloat162float(h));
}
__device__ __forceinline__ uint32_t smem_u32(const void* p) {
    uint32_t a;
    asm("{ .reg .u64 t; cvta.to.shared.u64 t, %1; cvt.u32.u64 %0, t; }" : "=r"(a) : "l"(p));
    return a;
}
__device__ __forceinline__ void hmma(float* c, const uint32_t* a,
                                     uint32_t b0, uint32_t b1) {
    asm("mma.sync.aligned.m16n8k16.row.col.f32.bf16.bf16.f32 "
        "{%0,%1,%2,%3}, {%4,%5,%6,%7}, {%8,%9}, {%0,%1,%2,%3};"
        : "+f"(c[0]), "+f"(c[1]), "+f"(c[2]), "+f"(c[3])
        : "r"(a[0]), "r"(a[1]), "r"(a[2]), "r"(a[3]), "r"(b0), "r"(b1));
}
__device__ __forceinline__ void ldsm_x4(uint32_t* a, uint32_t addr) {
    asm volatile("ldmatrix.sync.aligned.m8n8.x4.shared.b16 {%0,%1,%2,%3}, [%4];"
        : "=r"(a[0]), "=r"(a[1]), "=r"(a[2]), "=r"(a[3]) : "r"(addr));
}

// ============================================================
// Dense layer (layers 1 & 2): O = swish(A @ W^T + bias)
// 16 warps x 4 n8-tiles each; B frags via single LDG.128 with
// 1-deep register prefetch; term-major hmma order.
// ============================================================
template<int NKIT, int ASTR>
__device__ __forceinline__ void layer_dense(
    const __nv_bfloat16* Ah, const __nv_bfloat16* Al,
    const uint4* __restrict__ Wp,
    const float* bias,
    __nv_bfloat16* Oh, __nv_bfloat16* Ol,
    int warp, int lane)
{
    const int t4 = lane & 3;
    const int g = lane >> 2;
    const int nbase = warp * 32;

    float acc[8][4];
#pragma unroll
    for (int i = 0; i < 8; i++)
#pragma unroll
        for (int j = 0; j < 4; j++) acc[i][j] = 0.f;

    const uint32_t aAh = smem_u32(Ah), aAl = smem_u32(Al);
    const int roff0 = (((lane & 15)) * ASTR + ((lane >> 4) * 8)) * 2;
    const int roff1 = (((lane & 15) + 16) * ASTR + ((lane >> 4) * 8)) * 2;

    // warp's 4 tiles start at tile index warp*4
    const uint4* wbase = Wp + ((size_t)(warp * 4) * NKIT) * 32 + lane;

    uint4 bf[4];
#pragma unroll
    for (int nt = 0; nt < 4; nt++)
        bf[nt] = __ldg(wbase + (size_t)nt * NKIT * 32);

#pragma unroll
    for (int kit = 0; kit < NKIT; kit++) {
        const int kb = kit * 32;
        uint32_t ah[2][4], al[2][4];
        ldsm_x4(ah[0], aAh + roff0 + kb);
        ldsm_x4(ah[1], aAh + roff1 + kb);
        ldsm_x4(al[0], aAl + roff0 + kb);
        ldsm_x4(al[1], aAl + roff1 + kb);

        uint4 bn[4];
        if (kit + 1 < NKIT) {
#pragma unroll
            for (int nt = 0; nt < 4; nt++)
                bn[nt] = __ldg(wbase + ((size_t)nt * NKIT + kit + 1) * 32);
        }
        // term 1: Ah*Wh
#pragma unroll
        for (int nt = 0; nt < 4; nt++)
#pragma unroll
            for (int mt = 0; mt < 2; mt++)
                hmma(acc[nt * 2 + mt], ah[mt], bf[nt].x, bf[nt].y);
        // term 2: Al*Wh
#pragma unroll
        for (int nt = 0; nt < 4; nt++)
#pragma unroll
            for (int mt = 0; mt < 2; mt++)
                hmma(acc[nt * 2 + mt], al[mt], bf[nt].x, bf[nt].y);
        // term 3: Ah*Wl
#pragma unroll
        for (int nt = 0; nt < 4; nt++)
#pragma unroll
            for (int mt = 0; mt < 2; mt++)
                hmma(acc[nt * 2 + mt], ah[mt], bf[nt].z, bf[nt].w);

        if (kit + 1 < NKIT) {
#pragma unroll
            for (int nt = 0; nt < 4; nt++) bf[nt] = bn[nt];
        }
    }
    __syncthreads();   // all activation reads done before overwrite
#pragma unroll
    for (int nt = 0; nt < 4; nt++)
#pragma unroll
        for (int mt = 0; mt < 2; mt++) {
            float* c = acc[nt * 2 + mt];
            const int c0 = nbase + nt * 8 + t4 * 2;
            const int r0 = mt * 16 + g;
            const float bv0 = bias[c0], bv1 = bias[c0 + 1];
            split_store(Oh, Ol, r0 * HS + c0,           swishf(c[0] + bv0));
            split_store(Oh, Ol, r0 * HS + c0 + 1,       swishf(c[1] + bv1));
            split_store(Oh, Ol, (r0 + 8) * HS + c0,     swishf(c[2] + bv0));
            split_store(Oh, Ol, (r0 + 8) * HS + c0 + 1, swishf(c[3] + bv1));
        }
}

// ============================================================
// Persistent rollout
// ============================================================
__global__ void __launch_bounds__(NTHREADS) rollout_kernel(
    const float* __restrict__ obs,
    const float* __restrict__ acts,
    const float* __restrict__ b1, const float* __restrict__ b2,
    const float* __restrict__ b3,
    const float* __restrict__ maxlv, const float* __restrict__ minlv,
    const float* __restrict__ noise,
    float* __restrict__ out_obs,
    float* __restrict__ out_rew)
{
    const int tile = blockIdx.x;
    if (tile >= g_ntiles) return;
    const int nrows = g_tileRows[tile];
    const int km    = g_tileK[tile];
    const int start = g_tileStart[tile];

    extern __shared__ char sm[];
    __nv_bfloat16* Hh = (__nv_bfloat16*)(sm + OFF_HH);
    __nv_bfloat16* Hl = (__nv_bfloat16*)(sm + OFF_HL);
    __nv_bfloat16* Xh = (__nv_bfloat16*)(sm + OFF_XH);
    __nv_bfloat16* Xl = (__nv_bfloat16*)(sm + OFF_XL);
    float* sh_out = (float*)(sm + OFF_OUT);
    float* sb1 = (float*)(sm + OFF_B1);
    float* sb2 = (float*)(sm + OFF_B2);
    float* sb3 = (float*)(sm + OFF_B3);
    __shared__ int rows[TM];

    const int tid  = threadIdx.x;
    const int warp = tid >> 5, lane = tid & 31;
    const int g = lane >> 2, t4 = lane & 3;

    if (tid < TM) rows[tid] = (tid < nrows) ? g_perm[start + tid] : 0;

    for (int i = tid; i < HID; i += NTHREADS) {
        sb1[i] = b1[(size_t)km * HID + i];
        sb2[i] = b2[(size_t)km * HID + i];
    }
    for (int i = tid; i < N3PAD; i += NTHREADS)
        sb3[i] = (i < OUTD) ? b3[(size_t)km * OUTD + i] : 0.f;

    const uint4* Wp1 = g_wp1 + (size_t)km * NT1 * NKIT1 * 32;
    const uint4* Wp2 = g_wp2 + (size_t)km * NT1 * NKIT2 * 32;
    const uint4* Wp3 = g_wp3 + (size_t)km * NT3 * NKIT3 * 32;

    __syncthreads();

    for (int i = tid; i < TM * XS; i += NTHREADS) {
        Xh[i] = __float2bfloat16(0.f);
        Xl[i] = __float2bfloat16(0.f);
    }
    __syncthreads();
    for (int idx = tid; idx < TM * OBS; idx += NTHREADS) {
        int r = idx >> 6, d = idx & 63;
        float v = (r < nrows) ? obs[(size_t)rows[r] * OBS + d] : 0.f;
        split_store(Xh, Xl, r * XS + d, v);
    }

    for (int t = 0; t < T_STEPS; t++) {
        for (int idx = tid; idx < TM * ACT; idx += NTHREADS) {
            int r = idx >> 4, a = idx & 15;
            float v = (r < nrows) ? acts[((size_t)rows[r] * T_STEPS + t) * ACT + a] : 0.f;
            split_store(Xh, Xl, r * XS + OBS + a, v);
        }
        __syncthreads();

        layer_dense<NKIT1, XS>(Xh, Xl, Wp1, sb1, Hh, Hl, warp, lane);
        __syncthreads();
        layer_dense<NKIT2, HS>(Hh, Hl, Wp2, sb2, Hh, Hl, warp, lane);
        __syncthreads();

        // ===== layer 3: h[32,512] @ W3 -> out[32,129] =====
        {
            float acc[2][2][4];
#pragma unroll
            for (int i = 0; i < 2; i++)
#pragma unroll
                for (int m = 0; m < 2; m++)
#pragma unroll
                    for (int j = 0; j < 4; j++) acc[i][m][j] = 0.f;
            const int ntiles = (warp == 0) ? 2 : 1;
            const int tn[2] = {warp, 16};

            const uint32_t aHh = smem_u32(Hh), aHl = smem_u32(Hl);
            const int roff0 = (((lane & 15)) * HS + ((lane >> 4) * 8)) * 2;
            const int roff1 = (((lane & 15) + 16) * HS + ((lane >> 4) * 8)) * 2;

            uint4 bf[2];
#pragma unroll
            for (int i = 0; i < 2; i++)
                if (i < ntiles)
                    bf[i] = __ldg(Wp3 + ((size_t)tn[i] * NKIT3) * 32 + lane);

#pragma unroll 4
            for (int kit = 0; kit < NKIT3; kit++) {
                const int kb = kit * 32;
                uint32_t ah[2][4], al[2][4];
                ldsm_x4(ah[0], aHh + roff0 + kb);
                ldsm_x4(ah[1], aHh + roff1 + kb);
                ldsm_x4(al[0], aHl + roff0 + kb);
                ldsm_x4(al[1], aHl + roff1 + kb);

                uint4 bn[2];
                if (kit + 1 < NKIT3)
#pragma unroll
                    for (int i = 0; i < 2; i++)
                        if (i < ntiles)
                            bn[i] = __ldg(Wp3 + ((size_t)tn[i] * NKIT3 + kit + 1) * 32 + lane);

#pragma unroll
                for (int i = 0; i < 2; i++)
                    if (i < ntiles)
#pragma unroll
                        for (int mt = 0; mt < 2; mt++)
                            hmma(acc[i][mt], ah[mt], bf[i].x, bf[i].y);
#pragma unroll
                for (int i = 0; i < 2; i++)
                    if (i < ntiles)
#pragma unroll
                        for (int mt = 0; mt < 2; mt++)
                            hmma(acc[i][mt], al[mt], bf[i].x, bf[i].y);
#pragma unroll
                for (int i = 0; i < 2; i++)
                    if (i < ntiles)
#pragma unroll
                        for (int mt = 0; mt < 2; mt++)
                            hmma(acc[i][mt], ah[mt], bf[i].z, bf[i].w);

                if (kit + 1 < NKIT3) { bf[0] = bn[0]; bf[1] = bn[1]; }
            }
            __syncthreads();
            for (int i = 0; i < ntiles; i++) {
                const int c0 = tn[i] * 8 + t4 * 2;
#pragma unroll
                for (int mt = 0; mt < 2; mt++) {
                    float* c = acc[i][mt];
                    const int r0 = mt * 16 + g;
                    if (c0 < OUT_STRIDE) {
                        sh_out[r0 * OUT_STRIDE + c0]       = c[0] + sb3[c0];
                        sh_out[(r0 + 8) * OUT_STRIDE + c0] = c[2] + sb3[c0];
                    }
                    if (c0 + 1 < OUT_STRIDE) {
                        sh_out[r0 * OUT_STRIDE + c0 + 1]       = c[1] + sb3[c0 + 1];
                        sh_out[(r0 + 8) * OUT_STRIDE + c0 + 1] = c[3] + sb3[c0 + 1];
                    }
                }
            }
        }
        __syncthreads();

        // ===== postprocess =====
        const float* nz_t = noise + ((size_t)t * K_ENS + km) * B_TOT * OBS;
        for (int idx = tid; idx < TM * OBS; idx += NTHREADS) {
            int r = idx >> 6, d = idx & 63;
            if (r < nrows) {
                int row = rows[r];
                float mean = sh_out[r * OUT_STRIDE + d];
                float lv   = sh_out[r * OUT_STRIDE + OBS + d];
                float mx = __ldg(maxlv + d), mn = __ldg(minlv + d);
                lv = mx - softplusf(mx - lv);
                lv = mn + softplusf(lv - mn);
                float nz = __ldg(nz_t + (size_t)row * OBS + d);
                float no = fmaf(nz, __expf(0.5f * lv), mean);
                out_obs[((size_t)row * T_STEPS + t) * OBS + d] = no;
                split_store(Xh, Xl, r * XS + d, no);
            }
        }
        if (tid < nrows)
            out_rew[(size_t)rows[tid] * T_STEPS + t] = sh_out[tid * OUT_STRIDE + 128];
        __syncthreads();
    }
}

// ============================================================
// Launch
// ============================================================
extern "C" void kernel_launch(void* const* d_in, const int* in_sizes, int n_in,
                              void* d_out, int out_size) {
    const float* obs   = (const float*)d_in[0];
    const float* acts  = (const float*)d_in[1];
    const float* W1    = (const float*)d_in[2];
    const float* b1    = (const float*)d_in[3];
    const float* W2    = (const float*)d_in[4];
    const float* b2    = (const float*)d_in[5];
    const float* W3    = (const float*)d_in[6];
    const float* b3    = (const float*)d_in[7];
    const float* maxlv = (const float*)d_in[8];
    const float* minlv = (const float*)d_in[9];
    const float* noise = (const float*)d_in[10];
    const int*   assign_raw = (const int*)d_in[11];

    float* out_obs = (float*)d_out;
    float* out_rew = out_obs + (size_t)B_TOT * T_STEPS * OBS;

    uint4 *wp1, *wp2, *wp3;
    cudaGetSymbolAddress((void**)&wp1, g_wp1);
    cudaGetSymbolAddress((void**)&wp2, g_wp2);
    cudaGetSymbolAddress((void**)&wp3, g_wp3);

    cudaFuncSetAttribute(rollout_kernel,
                         cudaFuncAttributeMaxDynamicSharedMemorySize, SMEM_BYTES);

    setup_kernel<<<1, SETUP_THREADS>>>(assign_raw);

    {
        int tot1 = NT1 * NKIT1 * 32;   // 10240
        pack_frags<<<dim3((tot1 + 255) / 256, 1, K_ENS), 256>>>(W1, wp1, IN1, HID, HID);
        int tot2 = NT1 * NKIT2 * 32;   // 65536
        pack_frags<<<dim3((tot2 + 255) / 256, 1, K_ENS), 256>>>(W2, wp2, HID, HID, HID);
        int tot3 = NT3 * NKIT3 * 32;   // 17408
        pack_frags<<<dim3((tot3 + 255) / 256, 1, K_ENS), 256>>>(W3, wp3, HID, OUTD, N3PAD);
    }

    rollout_kernel<<<MAXTILES, NTHREADS, SMEM_BYTES>>>(
        obs, acts, b1, b2, b3, maxlv, minlv, noise, out_obs, out_rew);
}